// round 12
// baseline (speedup 1.0000x reference)
#include <cuda_runtime.h>
#include <cuda_fp16.h>
#include <cstdint>

#define N_ROWS   16384
#define N_CODES  8192
#define DIM      64
#define BM       128
#define BN       64
#define NCHUNK   (N_CODES / BN)      // 128
#define THREADS  256
#define ROWB     144                  // 9*16B; 9 mod 8 = 1 -> conflict-free LDSM
#define CGSTRIDE (16 * ROWB)
#define BSTG     (BN * ROWB)          // 9216 B per B stage
#define QCAP     8192
#define NARG     (N_ROWS / BM)        // 128 argmin CTAs
#define NZERO    128
#define DISC_F4  ((size_t)N_ROWS * N_CODES / 4)

// smem offsets
#define OFF_A    0
#define OFF_B    18432
#define OFF_Q    36864                 // QCAP * 4 = 32768
#define OFF_RED  69632                 // 128 * 8
#define OFF_XN   70656                 // 128 * 4
#define OFF_CNT  71168
#define SMEMSZ   71296

// device scratch
__device__ __align__(16) __half g_cbh[(size_t)N_CODES * DIM];  // fp16 hi only
__device__ __align__(16) float  g_cnorm[N_CODES];
__device__ unsigned g_cmax_u;          // max code sq-norm (float bits)
__device__ int g_idx[N_ROWS];

// ---------------- helpers ----------------
__device__ __forceinline__ uint32_t h2_as_u32(__half2 h) {
    uint32_t u; __builtin_memcpy(&u, &h, 4); return u;
}
__device__ __forceinline__ uint32_t pack_h2(__half a, __half b) {
    return h2_as_u32(__halves2half2(a, b));
}
__device__ __forceinline__ uint32_t smem_u32(const void* p) {
    uint32_t a;
    asm("{ .reg .u64 t; cvta.to.shared.u64 t, %1; cvt.u32.u64 %0, t; }" : "=r"(a) : "l"(p));
    return a;
}
__device__ __forceinline__ unsigned ord_f32(float f) {
    unsigned u = __float_as_uint(f);
    return (u & 0x80000000u) ? ~u : (u | 0x80000000u);
}
#define CPA16(d,s)   asm volatile("cp.async.cg.shared.global [%0], [%1], 16;" :: "r"(d), "l"(s) : "memory")
#define CPA_COMMIT() asm volatile("cp.async.commit_group;" ::: "memory")
#define CPA_WAIT0()  asm volatile("cp.async.wait_group 0;" ::: "memory")

#define LDM_X4(r0,r1,r2,r3,a) \
    asm volatile("ldmatrix.sync.aligned.m8n8.x4.shared.b16 {%0,%1,%2,%3}, [%4];" \
                 : "=r"(r0), "=r"(r1), "=r"(r2), "=r"(r3) : "r"(a))

__device__ __forceinline__ void mma16816(float* d, const uint32_t* a,
                                         uint32_t b0, uint32_t b1) {
    asm volatile("mma.sync.aligned.m16n8k16.row.col.f32.f16.f16.f32 "
                 "{%0,%1,%2,%3}, {%4,%5,%6,%7}, {%8,%9}, {%0,%1,%2,%3};"
                 : "+f"(d[0]), "+f"(d[1]), "+f"(d[2]), "+f"(d[3])
                 : "r"(a[0]), "r"(a[1]), "r"(a[2]), "r"(a[3]), "r"(b0), "r"(b1));
}

// ---------------------------------------------------------------------------
__global__ void init_kernel() { g_cmax_u = 0u; }

// Prep: codebook -> fp16 hi + squared norms + global max norm.
__global__ void prep_kernel(const float* __restrict__ cb) {
    int g = blockIdx.x * blockDim.x + threadIdx.x;
    int code = g >> 5, lane = g & 31;
    float2 v = reinterpret_cast<const float2*>(cb + (size_t)code * DIM)[lane];
    __half2* dst = reinterpret_cast<__half2*>(g_cbh + (size_t)code * DIM);
    dst[lane] = __halves2half2(__float2half_rn(v.x), __float2half_rn(v.y));
    float s = v.x * v.x + v.y * v.y;
#pragma unroll
    for (int o = 16; o; o >>= 1) s += __shfl_xor_sync(~0u, s, o);
    if (lane == 0) {
        g_cnorm[code] = s;
        atomicMax(&g_cmax_u, __float_as_uint(s));
    }
}

// exact fp32 rescore of one queue entry
__device__ __forceinline__ void rescore(uint32_t e, int row0,
                                        const float* __restrict__ x,
                                        const float* __restrict__ cb,
                                        unsigned long long* red) {
    int rl = e >> 13;
    int col = e & 8191;
    const float4* xr = reinterpret_cast<const float4*>(x + (size_t)(row0 + rl) * DIM);
    const float4* cr = reinterpret_cast<const float4*>(cb + (size_t)col * DIM);
    float s = 0.f;
#pragma unroll
    for (int i = 0; i < 16; i++) {
        float4 a = __ldg(xr + i), b = __ldg(cr + i);
        s = fmaf(a.x, b.x, s); s = fmaf(a.y, b.y, s);
        s = fmaf(a.z, b.z, s); s = fmaf(a.w, b.w, s);
    }
    float dist = fmaf(-2.f, s, __ldg(&g_cnorm[col]));
    unsigned long long key = ((unsigned long long)ord_f32(dist) << 32) | (unsigned)col;
    atomicMin(&red[rl], key);
}

// ---------------------------------------------------------------------------
// Fused: bid < NARG -> single-pass fp16 approx scan, R9-style immediate
//        per-f epilogue with queue-push in the taken arm; exact rescore.
//        bid >= NARG -> zerofill the one-hot output.
// ---------------------------------------------------------------------------
__global__ void __launch_bounds__(THREADS, 1)
argmin_fused(const float* __restrict__ x, const float* __restrict__ cb,
             float* __restrict__ out_disc) {
    const int tid = threadIdx.x;

    if (blockIdx.x >= NARG) {
        size_t i = (size_t)(blockIdx.x - NARG) * THREADS + tid;
        const size_t stride = (size_t)NZERO * THREADS;
        float4 z = make_float4(0.f, 0.f, 0.f, 0.f);
        float4* o = reinterpret_cast<float4*>(out_disc);
#pragma unroll 4
        for (; i < DISC_F4; i += stride) __stcs(o + i, z);
        return;
    }

    extern __shared__ char smem[];
    const uint32_t As = smem_u32(smem) + OFF_A;
    const uint32_t Bs = smem_u32(smem) + OFF_B;
    uint32_t* queue = reinterpret_cast<uint32_t*>(smem + OFF_Q);
    unsigned long long* red = reinterpret_cast<unsigned long long*>(smem + OFF_RED);
    float* xn = reinterpret_cast<float*>(smem + OFF_XN);
    int* cnt = reinterpret_cast<int*>(smem + OFF_CNT);

    const int wid = tid >> 5, lane = tid & 31;
    const int row0 = blockIdx.x * BM;
    const int r0l = wid * 16 + (lane >> 2);
    const int r1l = r0l + 8;

    if (tid < BM) { red[tid] = ~0ULL; xn[tid] = 0.f; }
    if (tid == 0) *cnt = 0;
    __syncthreads();

    // ---- stage A (fp16 hi) + row norms ----
    for (int t = tid; t < BM * (DIM / 4); t += THREADS) {
        int row = t >> 4, q = t & 15;
        float4 v = reinterpret_cast<const float4*>(x)[(size_t)(row0 + row) * 16 + q];
        uint32_t hp0 = pack_h2(__float2half_rn(v.x), __float2half_rn(v.y));
        uint32_t hp1 = pack_h2(__float2half_rn(v.z), __float2half_rn(v.w));
        uint32_t base = As + row * ROWB + q * 8;
        asm volatile("st.shared.v2.b32 [%0], {%1,%2};" :: "r"(base), "r"(hp0), "r"(hp1));
        float p = v.x * v.x + v.y * v.y + v.z * v.z + v.w * v.w;
        atomicAdd(&xn[row], p);
    }
    __syncthreads();

    // per-row margins (2M): covers |d_approx - d_exact| with slack (validated R11)
    const float cmaxf = sqrtf(__uint_as_float(g_cmax_u));
    const float m2_0 = 2.f * (ldexpf(sqrtf(xn[r0l]) * cmaxf, -9) * 1.1f + 1e-3f);
    const float m2_1 = 2.f * (ldexpf(sqrtf(xn[r1l]) * cmaxf, -9) * 1.1f + 1e-3f);

    // ---- persistent A fragments: 4 kgroups (xh only) ----
    uint32_t afr[4][4];
    {
        int t = lane >> 3;
        int arow = wid * 16 + ((t & 1) << 3) + (lane & 7);
        uint32_t abase = As + arow * ROWB + ((t >> 1) << 4);
#pragma unroll
        for (int kg = 0; kg < 4; kg++)
            LDM_X4(afr[kg][0], afr[kg][1], afr[kg][2], afr[kg][3], abase + kg * 32);
    }
    __syncthreads();

    const uint32_t bl0 = Bs + (((lane >> 4) << 3) + (lane & 7)) * ROWB
                       + ((lane >> 3) & 1) * 16;

    // ---- prefetch chunk 0 ----
    {
#pragma unroll
        for (int j = 0; j < 2; j++) {
            int i = tid + j * THREADS;
            int code = i >> 3, off = (i & 7) * 16;
            CPA16(Bs + code * ROWB + off, (const char*)g_cbh + i * 16);
        }
        CPA_COMMIT();
    }

    float best0 = 3.4e38f, best1 = 3.4e38f;
    float th0 = 3.4e38f, th1 = 3.4e38f;

    for (int c = 0; c < NCHUNK; c++) {
        CPA_WAIT0();
        __syncthreads();
        if (c + 1 < NCHUNK) {
            const char* src = (const char*)g_cbh + (size_t)(c + 1) * BN * 128;
            uint32_t dbuf = Bs + ((c + 1) & 1) * BSTG;
#pragma unroll
            for (int j = 0; j < 2; j++) {
                int i = tid + j * THREADS;
                int code = i >> 3, off = (i & 7) * 16;
                CPA16(dbuf + code * ROWB + off, src + i * 16);
            }
            CPA_COMMIT();
        }

        // safety drain (uniform branch; rare)
        int pending = *cnt;
        if (pending > 2048) {
            int n = pending < QCAP ? pending : QCAP;
            for (int i = tid; i < n; i += THREADS) rescore(queue[i], row0, x, cb, red);
            __syncthreads();
            if (tid == 0) *cnt = 0;
            __syncthreads();
        }

        const uint32_t bb = bl0 + (c & 1) * BSTG;
        float acc[8][4];
#pragma unroll
        for (int f = 0; f < 8; f++)
#pragma unroll
            for (int j = 0; j < 4; j++) acc[f][j] = 0.f;

#pragma unroll
        for (int kg = 0; kg < 4; kg++) {
            uint32_t b[4][4];
#pragma unroll
            for (int cg = 0; cg < 4; cg++)
                LDM_X4(b[cg][0], b[cg][1], b[cg][2], b[cg][3],
                       bb + cg * CGSTRIDE + kg * 32);
#pragma unroll
            for (int cg = 0; cg < 4; cg++) {
                mma16816(acc[2 * cg],     afr[kg], b[cg][0], b[cg][1]);
                mma16816(acc[2 * cg + 1], afr[kg], b[cg][2], b[cg][3]);
            }
        }

        // R9-style immediate per-f epilogue; queue push in the taken arm
        int cbase = c * BN + ((lane & 3) << 1);
#pragma unroll
        for (int f = 0; f < 8; f++) {
            int col = cbase + f * 8;
            float cn0 = __ldg(&g_cnorm[col]);
            float cn1 = __ldg(&g_cnorm[col + 1]);
            float d0 = fmaf(-2.f, acc[f][0], cn0);   // r0, col
            float d1 = fmaf(-2.f, acc[f][1], cn1);   // r0, col+1
            float d2 = fmaf(-2.f, acc[f][2], cn0);   // r1, col
            float d3 = fmaf(-2.f, acc[f][3], cn1);   // r1, col+1
            if (d0 <= th0) {
                int qi = atomicAdd(cnt, 1);
                if (qi < QCAP) queue[qi] = (uint32_t)((r0l << 13) | col);
                if (d0 < best0) { best0 = d0; th0 = best0 + m2_0; }
            }
            if (d1 <= th0) {
                int qi = atomicAdd(cnt, 1);
                if (qi < QCAP) queue[qi] = (uint32_t)((r0l << 13) | (col + 1));
                if (d1 < best0) { best0 = d1; th0 = best0 + m2_0; }
            }
            if (d2 <= th1) {
                int qi = atomicAdd(cnt, 1);
                if (qi < QCAP) queue[qi] = (uint32_t)((r1l << 13) | col);
                if (d2 < best1) { best1 = d2; th1 = best1 + m2_1; }
            }
            if (d3 <= th1) {
                int qi = atomicAdd(cnt, 1);
                if (qi < QCAP) queue[qi] = (uint32_t)((r1l << 13) | (col + 1));
                if (d3 < best1) { best1 = d3; th1 = best1 + m2_1; }
            }
        }
    }

    // ---- final drain + index write ----
    __syncthreads();
    {
        int pending = *cnt;
        int n = pending < QCAP ? pending : QCAP;
        for (int i = tid; i < n; i += THREADS) rescore(queue[i], row0, x, cb, red);
    }
    __syncthreads();
    if (tid < BM) g_idx[row0 + tid] = (int)(red[tid] & 0xffffffffu);
}

// ---------------------------------------------------------------------------
// Finalize: gather quantized rows + scatter the 1.0s into the one-hot.
// ---------------------------------------------------------------------------
__global__ void finalize_kernel(const float* __restrict__ cb,
                                float* __restrict__ out_disc,
                                float* __restrict__ outq) {
    unsigned i = blockIdx.x * 256u + threadIdx.x;
    unsigned n = i >> 4;
    unsigned c4 = i & 15u;
    int k = __ldg(&g_idx[n]);
    reinterpret_cast<float4*>(outq)[i] =
        reinterpret_cast<const float4*>(cb + (size_t)k * DIM)[c4];
    if (c4 == 0) out_disc[(size_t)n * N_CODES + k] = 1.0f;
}

// ---------------------------------------------------------------------------
extern "C" void kernel_launch(void* const* d_in, const int* in_sizes, int n_in,
                              void* d_out, int out_size) {
    const float* x  = (const float*)d_in[0];
    const float* cb = (const float*)d_in[1];
    float* out      = (float*)d_out;
    float* out_disc = out;
    float* out_q    = out + (size_t)N_ROWS * N_CODES;

    cudaFuncSetAttribute(argmin_fused, cudaFuncAttributeMaxDynamicSharedMemorySize, SMEMSZ);

    init_kernel<<<1, 1>>>();
    prep_kernel<<<(N_CODES * 32) / 256, 256>>>(cb);
    argmin_fused<<<NARG + NZERO, THREADS, SMEMSZ>>>(x, cb, out_disc);
    finalize_kernel<<<(N_ROWS * (DIM / 4)) / 256, 256>>>(cb, out_disc, out_q);
}

// round 13
// speedup vs baseline: 1.2902x; 1.2902x over previous
#include <cuda_runtime.h>
#include <cuda_fp16.h>
#include <cstdint>

#define N_ROWS   16384
#define N_CODES  8192
#define DIM      64
#define BM       128
#define BN       64
#define NCHUNK   (N_CODES / BN)      // 128
#define THREADS  256
#define ROWB     144                  // 9*16B; 9 mod 8 = 1 -> conflict-free LDSM
#define CGSTRIDE (16 * ROWB)
#define BSTG     (BN * ROWB)          // 9216 B per B stage
#define QSLOTS   64                   // per-thread private queue slots
#define NARG     (N_ROWS / BM)        // 128 argmin CTAs
#define NZERO    128
#define DISC_F4  ((size_t)N_ROWS * N_CODES / 4)

// smem offsets
#define OFF_A    0
#define OFF_B    18432
#define OFF_Q    36864                 // 256 threads * 64 slots * 4B = 65536
#define OFF_RED  102400                // 128 * 8
#define OFF_XN   103424                // 128 * 4
#define SMEMSZ   103936

// device scratch
__device__ __align__(16) __half g_cbh[(size_t)N_CODES * DIM];  // fp16 hi only
__device__ __align__(16) float  g_cnorm[N_CODES];
__device__ unsigned g_cmax_u;
__device__ int g_idx[N_ROWS];

// ---------------- helpers ----------------
__device__ __forceinline__ uint32_t h2_as_u32(__half2 h) {
    uint32_t u; __builtin_memcpy(&u, &h, 4); return u;
}
__device__ __forceinline__ uint32_t pack_h2(__half a, __half b) {
    return h2_as_u32(__halves2half2(a, b));
}
__device__ __forceinline__ uint32_t smem_u32(const void* p) {
    uint32_t a;
    asm("{ .reg .u64 t; cvta.to.shared.u64 t, %1; cvt.u32.u64 %0, t; }" : "=r"(a) : "l"(p));
    return a;
}
__device__ __forceinline__ unsigned ord_f32(float f) {
    unsigned u = __float_as_uint(f);
    return (u & 0x80000000u) ? ~u : (u | 0x80000000u);
}
#define CPA16(d,s)   asm volatile("cp.async.cg.shared.global [%0], [%1], 16;" :: "r"(d), "l"(s) : "memory")
#define CPA_COMMIT() asm volatile("cp.async.commit_group;" ::: "memory")
#define CPA_WAIT0()  asm volatile("cp.async.wait_group 0;" ::: "memory")

#define LDM_X4(r0,r1,r2,r3,a) \
    asm volatile("ldmatrix.sync.aligned.m8n8.x4.shared.b16 {%0,%1,%2,%3}, [%4];" \
                 : "=r"(r0), "=r"(r1), "=r"(r2), "=r"(r3) : "r"(a))

__device__ __forceinline__ void mma16816(float* d, const uint32_t* a,
                                         uint32_t b0, uint32_t b1) {
    asm volatile("mma.sync.aligned.m16n8k16.row.col.f32.f16.f16.f32 "
                 "{%0,%1,%2,%3}, {%4,%5,%6,%7}, {%8,%9}, {%0,%1,%2,%3};"
                 : "+f"(d[0]), "+f"(d[1]), "+f"(d[2]), "+f"(d[3])
                 : "r"(a[0]), "r"(a[1]), "r"(a[2]), "r"(a[3]), "r"(b0), "r"(b1));
}

// branch-free candidate push: predicated STS, no BSSY, no atomics
__device__ __forceinline__ void push_cand(uint32_t qbase, int& qn,
                                          float d, float& best, float& th,
                                          float m2, uint32_t entry) {
    int take;
    uint32_t addr = qbase + ((qn < QSLOTS - 1 ? qn : QSLOTS - 1) << 2);
    asm volatile("{ .reg .pred p; setp.le.f32 p, %1, %2; "
                 "@p st.shared.b32 [%3], %4; selp.b32 %0, 1, 0, p; }"
                 : "=r"(take) : "f"(d), "f"(th), "r"(addr), "r"(entry) : "memory");
    qn += take;
    best = fminf(best, d);
    th = best + m2;
}

// ---------------------------------------------------------------------------
__global__ void init_kernel() { g_cmax_u = 0u; }

__global__ void prep_kernel(const float* __restrict__ cb) {
    int g = blockIdx.x * blockDim.x + threadIdx.x;
    int code = g >> 5, lane = g & 31;
    float2 v = reinterpret_cast<const float2*>(cb + (size_t)code * DIM)[lane];
    __half2* dst = reinterpret_cast<__half2*>(g_cbh + (size_t)code * DIM);
    dst[lane] = __halves2half2(__float2half_rn(v.x), __float2half_rn(v.y));
    float s = v.x * v.x + v.y * v.y;
#pragma unroll
    for (int o = 16; o; o >>= 1) s += __shfl_xor_sync(~0u, s, o);
    if (lane == 0) {
        g_cnorm[code] = s;
        atomicMax(&g_cmax_u, __float_as_uint(s));
    }
}

// exact fp32 rescore of one queue entry
__device__ __forceinline__ void rescore(uint32_t e, int row0,
                                        const float* __restrict__ x,
                                        const float* __restrict__ cb,
                                        unsigned long long* red) {
    int rl = e >> 13;
    int col = e & 8191;
    const float4* xr = reinterpret_cast<const float4*>(x + (size_t)(row0 + rl) * DIM);
    const float4* cr = reinterpret_cast<const float4*>(cb + (size_t)col * DIM);
    float s = 0.f;
#pragma unroll
    for (int i = 0; i < 16; i++) {
        float4 a = __ldg(xr + i), b = __ldg(cr + i);
        s = fmaf(a.x, b.x, s); s = fmaf(a.y, b.y, s);
        s = fmaf(a.z, b.z, s); s = fmaf(a.w, b.w, s);
    }
    float dist = fmaf(-2.f, s, __ldg(&g_cnorm[col]));
    unsigned long long key = ((unsigned long long)ord_f32(dist) << 32) | (unsigned)col;
    atomicMin(&red[rl], key);
}

// ---------------------------------------------------------------------------
// Fused: bid < NARG -> single-pass fp16 approx scan with branch-free
//        per-thread candidate queues + exact fp32 rescore (drain every 32
//        chunks); bid >= NARG -> zerofill the one-hot output.
// ---------------------------------------------------------------------------
__global__ void __launch_bounds__(THREADS, 1)
argmin_fused(const float* __restrict__ x, const float* __restrict__ cb,
             float* __restrict__ out_disc) {
    const int tid = threadIdx.x;

    if (blockIdx.x >= NARG) {
        size_t i = (size_t)(blockIdx.x - NARG) * THREADS + tid;
        const size_t stride = (size_t)NZERO * THREADS;
        float4 z = make_float4(0.f, 0.f, 0.f, 0.f);
        float4* o = reinterpret_cast<float4*>(out_disc);
#pragma unroll 4
        for (; i < DISC_F4; i += stride) __stcs(o + i, z);
        return;
    }

    extern __shared__ char smem[];
    const uint32_t As = smem_u32(smem) + OFF_A;
    const uint32_t Bs = smem_u32(smem) + OFF_B;
    uint32_t* qs = reinterpret_cast<uint32_t*>(smem + OFF_Q);
    unsigned long long* red = reinterpret_cast<unsigned long long*>(smem + OFF_RED);
    float* xn = reinterpret_cast<float*>(smem + OFF_XN);

    const int wid = tid >> 5, lane = tid & 31;
    const int row0 = blockIdx.x * BM;
    const int r0l = wid * 16 + (lane >> 2);
    const int r1l = r0l + 8;
    const uint32_t qbase = smem_u32(smem) + OFF_Q + tid * (QSLOTS * 4);
    uint32_t* qsl = qs + tid * QSLOTS;
    int qn = 0;

    if (tid < BM) { red[tid] = ~0ULL; xn[tid] = 0.f; }
    __syncthreads();

    // ---- stage A (fp16 hi) + row norms ----
    for (int t = tid; t < BM * (DIM / 4); t += THREADS) {
        int row = t >> 4, q = t & 15;
        float4 v = reinterpret_cast<const float4*>(x)[(size_t)(row0 + row) * 16 + q];
        uint32_t hp0 = pack_h2(__float2half_rn(v.x), __float2half_rn(v.y));
        uint32_t hp1 = pack_h2(__float2half_rn(v.z), __float2half_rn(v.w));
        uint32_t base = As + row * ROWB + q * 8;
        asm volatile("st.shared.v2.b32 [%0], {%1,%2};" :: "r"(base), "r"(hp0), "r"(hp1));
        float p = v.x * v.x + v.y * v.y + v.z * v.z + v.w * v.w;
        atomicAdd(&xn[row], p);
    }
    __syncthreads();

    // per-row margins (2M): validated in R11/R12 (rel_err 0.0)
    const float cmaxf = sqrtf(__uint_as_float(g_cmax_u));
    const float m2_0 = 2.f * (ldexpf(sqrtf(xn[r0l]) * cmaxf, -9) * 1.1f + 1e-3f);
    const float m2_1 = 2.f * (ldexpf(sqrtf(xn[r1l]) * cmaxf, -9) * 1.1f + 1e-3f);

    // ---- persistent A fragments: 4 kgroups (xh only) ----
    uint32_t afr[4][4];
    {
        int t = lane >> 3;
        int arow = wid * 16 + ((t & 1) << 3) + (lane & 7);
        uint32_t abase = As + arow * ROWB + ((t >> 1) << 4);
#pragma unroll
        for (int kg = 0; kg < 4; kg++)
            LDM_X4(afr[kg][0], afr[kg][1], afr[kg][2], afr[kg][3], abase + kg * 32);
    }
    __syncthreads();

    const uint32_t bl0 = Bs + (((lane >> 4) << 3) + (lane & 7)) * ROWB
                       + ((lane >> 3) & 1) * 16;

    // ---- prefetch chunk 0 ----
    {
#pragma unroll
        for (int j = 0; j < 2; j++) {
            int i = tid + j * THREADS;
            int code = i >> 3, off = (i & 7) * 16;
            CPA16(Bs + code * ROWB + off, (const char*)g_cbh + i * 16);
        }
        CPA_COMMIT();
    }

    float best0 = 3.4e38f, best1 = 3.4e38f;
    float th0 = 3.4e38f, th1 = 3.4e38f;

    for (int c = 0; c < NCHUNK; c++) {
        CPA_WAIT0();
        __syncthreads();
        if (c + 1 < NCHUNK) {
            const char* src = (const char*)g_cbh + (size_t)(c + 1) * BN * 128;
            uint32_t dbuf = Bs + ((c + 1) & 1) * BSTG;
#pragma unroll
            for (int j = 0; j < 2; j++) {
                int i = tid + j * THREADS;
                int code = i >> 3, off = (i & 7) * 16;
                CPA16(dbuf + code * ROWB + off, src + i * 16);
            }
            CPA_COMMIT();
        }

        const uint32_t bb = bl0 + (c & 1) * BSTG;
        float acc[8][4];
#pragma unroll
        for (int f = 0; f < 8; f++)
#pragma unroll
            for (int j = 0; j < 4; j++) acc[f][j] = 0.f;

#pragma unroll
        for (int kg = 0; kg < 4; kg++) {
            uint32_t b[4][4];
#pragma unroll
            for (int cg = 0; cg < 4; cg++)
                LDM_X4(b[cg][0], b[cg][1], b[cg][2], b[cg][3],
                       bb + cg * CGSTRIDE + kg * 32);
#pragma unroll
            for (int cg = 0; cg < 4; cg++) {
                mma16816(acc[2 * cg],     afr[kg], b[cg][0], b[cg][1]);
                mma16816(acc[2 * cg + 1], afr[kg], b[cg][2], b[cg][3]);
            }
        }

        // branch-free epilogue: dist + predicated candidate push
        int cbase = c * BN + ((lane & 3) << 1);
        uint32_t e0 = (uint32_t)((r0l << 13) | cbase);
        uint32_t e1 = (uint32_t)((r1l << 13) | cbase);
#pragma unroll
        for (int f = 0; f < 8; f++) {
            int col = cbase + f * 8;
            float cn0 = __ldg(&g_cnorm[col]);
            float cn1 = __ldg(&g_cnorm[col + 1]);
            float d0 = fmaf(-2.f, acc[f][0], cn0);
            float d1 = fmaf(-2.f, acc[f][1], cn1);
            float d2 = fmaf(-2.f, acc[f][2], cn0);
            float d3 = fmaf(-2.f, acc[f][3], cn1);
            push_cand(qbase, qn, d0, best0, th0, m2_0, e0 + f * 8);
            push_cand(qbase, qn, d1, best0, th0, m2_0, e0 + f * 8 + 1);
            push_cand(qbase, qn, d2, best1, th1, m2_1, e1 + f * 8);
            push_cand(qbase, qn, d3, best1, th1, m2_1, e1 + f * 8 + 1);
        }

        // uniform periodic drain of the private queue (includes final chunk)
        if ((c & 31) == 31) {
            for (int i = 0; i < qn; i++) rescore(qsl[i], row0, x, cb, red);
            qn = 0;
        }
    }

    __syncthreads();
    if (tid < BM) g_idx[row0 + tid] = (int)(red[tid] & 0xffffffffu);
}

// ---------------------------------------------------------------------------
// Finalize: gather quantized rows + scatter the 1.0s into the one-hot.
// ---------------------------------------------------------------------------
__global__ void finalize_kernel(const float* __restrict__ cb,
                                float* __restrict__ out_disc,
                                float* __restrict__ outq) {
    unsigned i = blockIdx.x * 256u + threadIdx.x;
    unsigned n = i >> 4;
    unsigned c4 = i & 15u;
    int k = __ldg(&g_idx[n]);
    reinterpret_cast<float4*>(outq)[i] =
        reinterpret_cast<const float4*>(cb + (size_t)k * DIM)[c4];
    if (c4 == 0) out_disc[(size_t)n * N_CODES + k] = 1.0f;
}

// ---------------------------------------------------------------------------
extern "C" void kernel_launch(void* const* d_in, const int* in_sizes, int n_in,
                              void* d_out, int out_size) {
    const float* x  = (const float*)d_in[0];
    const float* cb = (const float*)d_in[1];
    float* out      = (float*)d_out;
    float* out_disc = out;
    float* out_q    = out + (size_t)N_ROWS * N_CODES;

    cudaFuncSetAttribute(argmin_fused, cudaFuncAttributeMaxDynamicSharedMemorySize, SMEMSZ);

    init_kernel<<<1, 1>>>();
    prep_kernel<<<(N_CODES * 32) / 256, 256>>>(cb);
    argmin_fused<<<NARG + NZERO, THREADS, SMEMSZ>>>(x, cb, out_disc);
    finalize_kernel<<<(N_ROWS * (DIM / 4)) / 256, 256>>>(cb, out_disc, out_q);
}